// round 15
// baseline (speedup 1.0000x reference)
#include <cuda_runtime.h>
#include <cuda_bf16.h>
#include <cuda_fp16.h>
#include <cstdint>
#include <math.h>

#define NN 100000
#define NE 600000
#define NG 512
#define HD 128
#define EF 256
#define NCONV 3
#define NB_SCAN 98

// ---- scratch (device globals) ----
__device__ float g_x[NN * HD];
__device__ __half g_xf[NN * HD];
__device__ __half g_Af[NN * EF];
__device__ __half g_sG[NN * HD];
__device__ __half g_M[NN * HD];
__device__ float g_y[NG * HD];
__device__ int g_cnt[NN];
__device__ int g_cur[NN];
__device__ int g_off[NN + 1];
__device__ int g_elist[NE];
__device__ int g_bsum[128];
__device__ int g_bpre[128];
#define WCAT(c) ((c) * 49152)
#define WPT 147456
#define WE2(c) (163840 + (c) * 32768)
__device__ __half g_Wfh[262144];
__device__ __half g_Wfl[262144];

__device__ __forceinline__ float sp_(float x) {
    return fmaxf(x, 0.f) + __logf(1.f + __expf(-fabsf(x)));
}
__device__ __forceinline__ float sigm_(float x) {
    return 1.f / (1.f + __expf(-x));
}

__global__ void k_wsplit_all(const float* __restrict__ Wg, const float* __restrict__ We1,
                             const float* __restrict__ We2, const float* __restrict__ Wp) {
    int i = blockIdx.x * blockDim.x + threadIdx.x;
    if (i >= 262144) return;
    float w;
    if (i < 147456) {
        int c = i / 49152, j = i % 49152;
        int n = j / HD, k = j % HD;
        w = (n < EF) ? We1[c * 32768 + k * EF + n]
                     : Wg[c * 16384 + k * HD + (n - EF)];
    } else if (i < 163840) {
        int j = i - 147456;
        int n = j / HD, k = j % HD;
        w = Wp[k * HD + n];
    } else {
        int j = i - 163840;
        int c = j / 32768, jj = j % 32768;
        int n = jj >> 8, k = jj & 255;
        w = We2[c * 32768 + k * HD + n];
    }
    __half h = __float2half_rn(w);
    __half l = __float2half_rn(w - __half2float(h));
    g_Wfh[i] = h;
    g_Wfl[i] = l;
}

__global__ void k_zero_misc() {
    int i = blockIdx.x * blockDim.x + threadIdx.x;
    if (i < NN) {
        g_cnt[i] = 0;
        g_cur[i] = 0;
    }
    if (i < NG * HD) g_y[i] = 0.f;
}

__global__ void k_hist(const int* __restrict__ tgt) {
    int i = blockIdx.x * blockDim.x + threadIdx.x;
    if (i < NE) atomicAdd(&g_cnt[tgt[i]], 1);
}

__global__ void k_scan1() {
    __shared__ int wsum[32];
    const int tid = threadIdx.x;
    const int lane = tid & 31;
    const int wid = tid >> 5;
    const int i = blockIdx.x * 1024 + tid;
    int v = (i < NN) ? g_cnt[i] : 0;
    int inc = v;
#pragma unroll
    for (int d = 1; d < 32; d <<= 1) {
        int t = __shfl_up_sync(0xFFFFFFFFu, inc, d);
        if (lane >= d) inc += t;
    }
    if (lane == 31) wsum[wid] = inc;
    __syncthreads();
    if (wid == 0) {
        int w = wsum[lane];
        int wi = w;
#pragma unroll
        for (int d = 1; d < 32; d <<= 1) {
            int t = __shfl_up_sync(0xFFFFFFFFu, wi, d);
            if (lane >= d) wi += t;
        }
        wsum[lane] = wi - w;
    }
    __syncthreads();
    int binc = wsum[wid] + inc;
    if (i < NN) g_off[i + 1] = binc;
    if (tid == 1023) g_bsum[blockIdx.x] = binc;
}

__global__ void k_scan2() {
    __shared__ int ws[4];
    const int tid = threadIdx.x;
    const int lane = tid & 31;
    const int wid = tid >> 5;
    int v = (tid < NB_SCAN) ? g_bsum[tid] : 0;
    int inc = v;
#pragma unroll
    for (int d = 1; d < 32; d <<= 1) {
        int t = __shfl_up_sync(0xFFFFFFFFu, inc, d);
        if (lane >= d) inc += t;
    }
    if (lane == 31) ws[wid] = inc;
    __syncthreads();
    if (tid == 0) {
        int a = 0;
#pragma unroll
        for (int w = 0; w < 4; w++) {
            int t = ws[w];
            ws[w] = a;
            a += t;
        }
    }
    __syncthreads();
    if (tid < NB_SCAN) g_bpre[tid] = ws[wid] + inc - v;
}

__global__ void k_scan3() {
    int i = blockIdx.x * blockDim.x + threadIdx.x;
    if (i == 0) g_off[0] = 0;
    if (i < NN) g_off[i + 1] += g_bpre[i >> 10];
}

__global__ void k_fill(const int* __restrict__ src, const int* __restrict__ tgt) {
    int i = blockIdx.x * blockDim.x + threadIdx.x;
    if (i >= NE) return;
    int t = tgt[i];
    int p = g_off[t] + atomicAdd(&g_cur[t], 1);
    g_elist[p] = src[i];
}

__global__ void k_embed(const int* __restrict__ nodes, const float* __restrict__ embed) {
    int i = blockIdx.x * blockDim.x + threadIdx.x;
    if (i >= NN * (HD / 4)) return;
    int node = nodes[i >> 5];
    float4 v = ((const float4*)embed)[node * 32 + (i & 31)];
    ((float4*)g_x)[i] = v;
    ((__half2*)g_xf)[i * 2] = __floats2half2_rn(v.x, v.y);
    ((__half2*)g_xf)[i * 2 + 1] = __floats2half2_rn(v.z, v.w);
}

// ---- PTX helpers ----
#define LDA 40

__device__ __forceinline__ void cp16(uint32_t dst, const void* src, bool pred) {
    int sz = pred ? 16 : 0;
    asm volatile("cp.async.cg.shared.global [%0], [%1], 16, %2;"
                 :: "r"(dst), "l"(src), "r"(sz));
}
__device__ __forceinline__ void cp_commit() {
    asm volatile("cp.async.commit_group;");
}
template <int N_>
__device__ __forceinline__ void cp_wait() {
    asm volatile("cp.async.wait_group %0;" :: "n"(N_));
}
__device__ __forceinline__ void ldm_x4(uint32_t addr, uint32_t r[4]) {
    asm volatile("ldmatrix.sync.aligned.m8n8.x4.shared.b16 {%0,%1,%2,%3},[%4];"
                 : "=r"(r[0]), "=r"(r[1]), "=r"(r[2]), "=r"(r[3]) : "r"(addr));
}
__device__ __forceinline__ void mma_f16(float c[4], const uint32_t a[4],
                                        uint32_t b0, uint32_t b1) {
    asm volatile(
        "mma.sync.aligned.m16n8k16.row.col.f32.f16.f16.f32 "
        "{%0,%1,%2,%3},{%4,%5,%6,%7},{%8,%9},{%0,%1,%2,%3};"
        : "+f"(c[0]), "+f"(c[1]), "+f"(c[2]), "+f"(c[3])
        : "r"(a[0]), "r"(a[1]), "r"(a[2]), "r"(a[3]), "r"(b0), "r"(b1));
}

// ======================================================================
// A-RESIDENT fp16 2-term GEMM: whole 128xK A panel loaded to smem once,
// internal loop over NTILES 64-wide n-tiles (B double-buffered; next
// tile's B0 prefetched in the last k-step).
// EPI: 3 atomicAdd Cf[gidx] ; 4 merged (n<256: Af softplus | sG sigmoid)
// ======================================================================
template <int EPI, int NTILES, int KT_>
__global__ void __launch_bounds__(256) k_g16ar(
    const __half* __restrict__ A, const __half* __restrict__ Bh,
    const __half* __restrict__ Bl, float* __restrict__ Cf,
    const int* __restrict__ gidx, __half* __restrict__ Out16,
    __half* __restrict__ Out2, int M) {
    constexpr int K = KT_;
    constexpr int T = K / 32;
    constexpr int LDA2 = K + 8;

    __shared__ __half sAr[128 * LDA2];
    __shared__ __half sB[2][2][64 * LDA];

    const int tid = threadIdx.x;
    const int lane = tid & 31;
    const int warp = tid >> 5;
    const int wm = warp >> 1;
    const int wn = warp & 1;
    const int m0 = blockIdx.x * 128;

    uint32_t aBr = (uint32_t)__cvta_generic_to_shared(sAr);
    uint32_t bB[2][2];
#pragma unroll
    for (int st = 0; st < 2; st++)
#pragma unroll
        for (int hl = 0; hl < 2; hl++)
            bB[st][hl] = (uint32_t)__cvta_generic_to_shared(&sB[st][hl][0]);

    const int b_r = tid >> 2;
    const int b_kc = (tid & 3) * 8;
    const uint32_t bOff = (uint32_t)(b_r * LDA + b_kc) * 2u;

    const int a_row = ((lane >> 3) & 1) * 8 + (lane & 7);
    const int a_kof = (lane >> 4) * 8;
    const int b_row = ((lane >> 4) & 1) * 8 + (lane & 7);
    const int b_kof = ((lane >> 3) & 1) * 8;

    // ---- load entire A panel (group 1) ----
    constexpr int CPR = K / 8;  // 16B chunks per row
#pragma unroll
    for (int it = 0; it < (128 * CPR) / 256; it++) {
        int idx = tid + it * 256;
        int row = idx / CPR;
        int cc = idx % CPR;
        bool p = (m0 + row) < M;
        const __half* src = A + (p ? ((long)(m0 + row) * K + cc * 8) : 0);
        cp16(aBr + (uint32_t)(row * LDA2 + cc * 8) * 2u, src, p);
    }
    cp_commit();

#define LOAD_B(st, k0, nn0)                                            \
    do {                                                               \
        const __half* pbh = Bh + (long)((nn0) + b_r) * K + b_kc + (k0); \
        const __half* pbl = Bl + (long)((nn0) + b_r) * K + b_kc + (k0); \
        cp16(bB[st][0] + bOff, pbh, true);                             \
        cp16(bB[st][1] + bOff, pbl, true);                             \
    } while (0)

    // B tile0 stage0 (group 2)
    LOAD_B(0, 0, 0);
    cp_commit();

#pragma unroll
    for (int nt = 0; nt < NTILES; nt++) {
        const int n0 = nt * 64;
        float acc[2][4][4];
#pragma unroll
        for (int i = 0; i < 2; i++)
#pragma unroll
            for (int j = 0; j < 4; j++)
#pragma unroll
                for (int q = 0; q < 4; q++) acc[i][j][q] = 0.f;

#pragma unroll
        for (int kt = 0; kt < T; kt++) {
            bool more = (kt + 1 < T) || (nt + 1 < NTILES);
            if (kt + 1 < T)
                LOAD_B((kt + 1) & 1, (kt + 1) * 32, n0);
            else if (nt + 1 < NTILES)
                LOAD_B(0, 0, n0 + 64);  // T even -> next tile starts on stage 0
            cp_commit();
            if (more) cp_wait<1>();
            else cp_wait<0>();
            __syncthreads();

            const int st = kt & 1;
#pragma unroll
            for (int ks = 0; ks < 32; ks += 16) {
                uint32_t fa[2][4], fbh[2][4], fbl[2][4];
#pragma unroll
                for (int mt = 0; mt < 2; mt++) {
                    uint32_t off = (uint32_t)((wm * 32 + mt * 16 + a_row) * LDA2 +
                                              kt * 32 + ks + a_kof) * 2u;
                    ldm_x4(aBr + off, fa[mt]);
                }
#pragma unroll
                for (int np = 0; np < 2; np++) {
                    uint32_t off = (uint32_t)((wn * 32 + np * 16 + b_row) * LDA +
                                              ks + b_kof) * 2u;
                    ldm_x4(bB[st][0] + off, fbh[np]);
                    ldm_x4(bB[st][1] + off, fbl[np]);
                }
#pragma unroll
                for (int term = 0; term < 2; term++) {
#pragma unroll
                    for (int mt = 0; mt < 2; mt++) {
#pragma unroll
                        for (int nt2 = 0; nt2 < 4; nt2++) {
                            uint32_t b0, b1;
                            if (term == 0) {
                                b0 = fbh[nt2 >> 1][(nt2 & 1) * 2];
                                b1 = fbh[nt2 >> 1][(nt2 & 1) * 2 + 1];
                            } else {
                                b0 = fbl[nt2 >> 1][(nt2 & 1) * 2];
                                b1 = fbl[nt2 >> 1][(nt2 & 1) * 2 + 1];
                            }
                            mma_f16(acc[mt][nt2], fa[mt], b0, b1);
                        }
                    }
                }
            }
            __syncthreads();
        }

        // epilogue for this n-tile
#pragma unroll
        for (int mt = 0; mt < 2; mt++) {
#pragma unroll
            for (int nt2 = 0; nt2 < 4; nt2++) {
                int rbase = m0 + wm * 32 + mt * 16 + (lane >> 2);
                int col = n0 + wn * 32 + nt2 * 8 + (lane & 3) * 2;
                float* c = acc[mt][nt2];
#pragma unroll
                for (int half = 0; half < 2; half++) {
                    int row = rbase + half * 8;
                    if (row >= M) continue;
                    float v0 = c[half * 2], v1 = c[half * 2 + 1];
                    if (EPI == 4 && n0 < 256) {
                        long base = (long)row * 256 + col;
                        *reinterpret_cast<__half2*>(&Out16[base]) =
                            __floats2half2_rn(sp_(v0), sp_(v1));
                    } else if (EPI == 4) {
                        long base = (long)row * HD + (col - 256);
                        *reinterpret_cast<__half2*>(&Out2[base]) =
                            __floats2half2_rn(sigm_(v0), sigm_(v1));
                    } else {  // EPI == 3
                        int seg = gidx[row];
                        atomicAdd(reinterpret_cast<float2*>(&Cf[(long)seg * HD + col]),
                                  make_float2(v0, v1));
                    }
                }
            }
        }
    }
#undef LOAD_B
}

// ======================================================================
// Standard fp16 2-term GEMM (message): M = Gb16 * softplus(A @ B^T)
// ======================================================================
template <int KT_>
__global__ void __launch_bounds__(256) k_g16(
    const __half* __restrict__ A, const __half* __restrict__ Bh,
    const __half* __restrict__ Bl, const __half* __restrict__ Gb16,
    __half* __restrict__ Out16, int M) {
    constexpr int K = KT_;
    constexpr int T = K / 32;

    __shared__ __half sA[2][128 * LDA];
    __shared__ __half sB[2][2][64 * LDA];

    const int tid = threadIdx.x;
    const int lane = tid & 31;
    const int warp = tid >> 5;
    const int wm = warp >> 1;
    const int wn = warp & 1;
    const int m0 = blockIdx.y * 128;
    const int n0 = blockIdx.x * 64;

    float acc[2][4][4];
#pragma unroll
    for (int i = 0; i < 2; i++)
#pragma unroll
        for (int j = 0; j < 4; j++)
#pragma unroll
            for (int q = 0; q < 4; q++) acc[i][j][q] = 0.f;

    uint32_t aB[2], bB[2][2];
#pragma unroll
    for (int st = 0; st < 2; st++) {
        aB[st] = (uint32_t)__cvta_generic_to_shared(&sA[st][0]);
#pragma unroll
        for (int hl = 0; hl < 2; hl++)
            bB[st][hl] = (uint32_t)__cvta_generic_to_shared(&sB[st][hl][0]);
    }

    const int a_r0 = tid >> 2;
    const int a_kc = (tid & 3) * 8;
    const int b_r = tid >> 2;
    const int b_kc = (tid & 3) * 8;

    const int a_row = ((lane >> 3) & 1) * 8 + (lane & 7);
    const int a_kof = (lane >> 4) * 8;
    const int b_row = ((lane >> 4) & 1) * 8 + (lane & 7);
    const int b_kof = ((lane >> 3) & 1) * 8;

    const bool pA0 = (m0 + a_r0) < M;
    const bool pA1 = (m0 + a_r0 + 64) < M;
    const uint32_t aOff0 = (uint32_t)(a_r0 * LDA + a_kc) * 2u;
    const uint32_t aOff1 = (uint32_t)((a_r0 + 64) * LDA + a_kc) * 2u;
    const uint32_t bOff = (uint32_t)(b_r * LDA + b_kc) * 2u;
    const __half* gA0 = A + (pA0 ? (long)(m0 + a_r0) * K + a_kc : 0);
    const __half* gA1 = A + (pA1 ? (long)(m0 + a_r0 + 64) * K + a_kc : 0);
    const __half* gBh = Bh + (long)(n0 + b_r) * K + b_kc;
    const __half* gBl = Bl + (long)(n0 + b_r) * K + b_kc;

#define LOAD_STAGE(st, k0)                           \
    do {                                             \
        cp16(aB[st] + aOff0, gA0 + (k0), pA0);       \
        cp16(aB[st] + aOff1, gA1 + (k0), pA1);       \
        cp16(bB[st][0] + bOff, gBh + (k0), true);    \
        cp16(bB[st][1] + bOff, gBl + (k0), true);    \
        cp_commit();                                 \
    } while (0)

    LOAD_STAGE(0, 0);

#pragma unroll
    for (int kt = 0; kt < T; kt++) {
        if (kt + 1 < T) {
            LOAD_STAGE((kt + 1) & 1, (kt + 1) * 32);
            cp_wait<1>();
        } else {
            cp_wait<0>();
        }
        __syncthreads();

        const int st = kt & 1;
#pragma unroll
        for (int ks = 0; ks < 32; ks += 16) {
            uint32_t fa[2][4], fbh[2][4], fbl[2][4];
#pragma unroll
            for (int mt = 0; mt < 2; mt++) {
                uint32_t off = (uint32_t)((wm * 32 + mt * 16 + a_row) * LDA + ks + a_kof) * 2u;
                ldm_x4(aB[st] + off, fa[mt]);
            }
#pragma unroll
            for (int np = 0; np < 2; np++) {
                uint32_t off = (uint32_t)((wn * 32 + np * 16 + b_row) * LDA + ks + b_kof) * 2u;
                ldm_x4(bB[st][0] + off, fbh[np]);
                ldm_x4(bB[st][1] + off, fbl[np]);
            }
#pragma unroll
            for (int term = 0; term < 2; term++) {
#pragma unroll
                for (int mt = 0; mt < 2; mt++) {
#pragma unroll
                    for (int nt = 0; nt < 4; nt++) {
                        uint32_t b0, b1;
                        if (term == 0) {
                            b0 = fbh[nt >> 1][(nt & 1) * 2];
                            b1 = fbh[nt >> 1][(nt & 1) * 2 + 1];
                        } else {
                            b0 = fbl[nt >> 1][(nt & 1) * 2];
                            b1 = fbl[nt >> 1][(nt & 1) * 2 + 1];
                        }
                        mma_f16(acc[mt][nt], fa[mt], b0, b1);
                    }
                }
            }
        }
        __syncthreads();
    }
#undef LOAD_STAGE

#pragma unroll
    for (int mt = 0; mt < 2; mt++) {
#pragma unroll
        for (int nt = 0; nt < 4; nt++) {
            int rbase = m0 + wm * 32 + mt * 16 + (lane >> 2);
            int col = n0 + wn * 32 + nt * 8 + (lane & 3) * 2;
            float* c = acc[mt][nt];
#pragma unroll
            for (int half = 0; half < 2; half++) {
                int row = rbase + half * 8;
                if (row >= M) continue;
                long base = (long)row * HD + col;
                float2 g2 = __half22float2(
                    *reinterpret_cast<const __half2*>(&Gb16[base]));
                *reinterpret_cast<__half2*>(&Out16[base]) =
                    __floats2half2_rn(g2.x * sp_(c[half * 2]), g2.y * sp_(c[half * 2 + 1]));
            }
        }
    }
}

// ---- CSR gather + fused node update ----
__global__ void __launch_bounds__(256) k_gather() {
    int warp = (blockIdx.x * 256 + threadIdx.x) >> 5;
    int lane = threadIdx.x & 31;
    if (warp >= NN) return;
    int beg = g_off[warp], end = g_off[warp + 1];

    float4 acc = make_float4(0.f, 0.f, 0.f, 0.f);
    int e = beg;
    for (; e + 1 < end; e += 2) {
        int s0 = g_elist[e], s1 = g_elist[e + 1];
        float2 p0 = *reinterpret_cast<const float2*>(&g_M[(long)s0 * HD + lane * 4]);
        float2 p1 = *reinterpret_cast<const float2*>(&g_M[(long)s1 * HD + lane * 4]);
        const __half2* h0 = reinterpret_cast<const __half2*>(&p0);
        const __half2* h1 = reinterpret_cast<const __half2*>(&p1);
        float2 a0 = __half22float2(h0[0]), b0 = __half22float2(h0[1]);
        float2 a1 = __half22float2(h1[0]), b1 = __half22float2(h1[1]);
        acc.x += a0.x + a1.x;
        acc.y += a0.y + a1.y;
        acc.z += b0.x + b1.x;
        acc.w += b0.y + b1.y;
    }
    if (e < end) {
        int s0 = g_elist[e];
        float2 p0 = *reinterpret_cast<const float2*>(&g_M[(long)s0 * HD + lane * 4]);
        const __half2* h0 = reinterpret_cast<const __half2*>(&p0);
        float2 a0 = __half22float2(h0[0]), b0 = __half22float2(h0[1]);
        acc.x += a0.x;
        acc.y += a0.y;
        acc.z += b0.x;
        acc.w += b0.y;
    }

    int i4 = warp * 32 + lane;
    float4 x = ((float4*)g_x)[i4];
    x.x += sp_(acc.x);
    x.y += sp_(acc.y);
    x.z += sp_(acc.z);
    x.w += sp_(acc.w);
    ((float4*)g_x)[i4] = x;
    ((__half2*)g_xf)[i4 * 2] = __floats2half2_rn(x.x, x.y);
    ((__half2*)g_xf)[i4 * 2 + 1] = __floats2half2_rn(x.z, x.w);
}

__global__ void k_mlp(const float* __restrict__ counts,
                      const float* __restrict__ Wfc1, const float* __restrict__ bfc1,
                      const float* __restrict__ Wfc2, const float* __restrict__ bfc2,
                      const float* __restrict__ Wr, const float* __restrict__ br,
                      float* __restrict__ out) {
    __shared__ float s0[HD];
    __shared__ float s1[HD];
    __shared__ float red[HD];
    int g = blockIdx.x, t = threadIdx.x;

    float yv = g_y[g * HD + t] / counts[g];
    s0[t] = sp_(yv);
    __syncthreads();

    float acc = bfc1[t];
#pragma unroll 8
    for (int k = 0; k < HD; k++) acc += s0[k] * Wfc1[k * HD + t];
    s1[t] = sp_(acc);
    __syncthreads();

    acc = bfc2[t];
#pragma unroll 8
    for (int k = 0; k < HD; k++) acc += s1[k] * Wfc2[k * HD + t];
    float h2 = sp_(acc);

    red[t] = h2 * Wr[t];
    __syncthreads();
    for (int s = HD / 2; s > 0; s >>= 1) {
        if (t < s) red[t] += red[t + s];
        __syncthreads();
    }
    if (t == 0) out[g] = red[0] + br[0];
}

extern "C" void kernel_launch(void* const* d_in, const int* in_sizes, int n_in,
                              void* d_out, int out_size) {
    const int* nodes = (const int*)d_in[0];
    const int* esrc = (const int*)d_in[1];
    const int* etgt = (const int*)d_in[2];
    const int* gidx = (const int*)d_in[3];
    const float* counts = (const float*)d_in[4];
    const float* embed = (const float*)d_in[5];
    const float* Wg = (const float*)d_in[6];
    const float* We1 = (const float*)d_in[7];
    const float* We2 = (const float*)d_in[8];
    const float* Wp = (const float*)d_in[9];
    const float* Wfc1 = (const float*)d_in[10];
    const float* bfc1 = (const float*)d_in[11];
    const float* Wfc2 = (const float*)d_in[12];
    const float* bfc2 = (const float*)d_in[13];
    const float* Wr = (const float*)d_in[14];
    const float* br = (const float*)d_in[15];
    float* out = (float*)d_out;

    __half *pxf, *pAf, *pWfh, *pWfl, *psG, *pM;
    float* py;
    cudaGetSymbolAddress((void**)&pxf, g_xf);
    cudaGetSymbolAddress((void**)&pAf, g_Af);
    cudaGetSymbolAddress((void**)&pWfh, g_Wfh);
    cudaGetSymbolAddress((void**)&pWfl, g_Wfl);
    cudaGetSymbolAddress((void**)&psG, g_sG);
    cudaGetSymbolAddress((void**)&pM, g_M);
    cudaGetSymbolAddress((void**)&py, g_y);

    const int blocksM = (NN + 127) / 128;

    k_wsplit_all<<<(262144 + 255) / 256, 256>>>(Wg, We1, We2, Wp);
    k_zero_misc<<<(NN + 255) / 256, 256>>>();
    k_hist<<<(NE + 255) / 256, 256>>>(etgt);
    k_scan1<<<NB_SCAN, 1024>>>();
    k_scan2<<<1, 128>>>();
    k_scan3<<<(NN + 1023) / 1024, 1024>>>();
    k_fill<<<(NE + 255) / 256, 256>>>(esrc, etgt);
    {
        int n = NN * (HD / 4);
        k_embed<<<(n + 255) / 256, 256>>>(nodes, embed);
    }
    for (int i = 0; i < NCONV; i++) {
        // merged A-resident: sp(x@We1) -> Af AND sigmoid(x@Wg) -> sG
        k_g16ar<4, 6, HD><<<blocksM, 256>>>(
            pxf, pWfh + WCAT(i), pWfl + WCAT(i),
            nullptr, nullptr, pAf, psG, NN);
        // M = sG * sp(A @ We2)
        k_g16<EF><<<dim3(HD / 64, blocksM), 256>>>(
            pAf, pWfh + WE2(i), pWfl + WE2(i), psG, pM, NN);
        k_gather<<<(NN + 7) / 8, 256>>>();
    }
    // pooling A-resident with fused segment atomics
    k_g16ar<3, 2, HD><<<blocksM, 256>>>(
        pxf, pWfh + WPT, pWfl + WPT,
        py, gidx, nullptr, nullptr, NN);
    k_mlp<<<NG, HD>>>(counts, Wfc1, bfc1, Wfc2, bfc2, Wr, br, out);
}

// round 16
// speedup vs baseline: 1.1964x; 1.1964x over previous
#include <cuda_runtime.h>
#include <cuda_bf16.h>
#include <cuda_fp16.h>
#include <cstdint>
#include <math.h>

#define NN 100000
#define NE 600000
#define NG 512
#define HD 128
#define EF 256
#define NCONV 3
#define NB_SCAN 98

// ---- scratch (device globals) ----
__device__ float g_x[NN * HD];
__device__ __half g_xf[NN * HD];
__device__ __half g_Af[NN * EF];
__device__ __half g_sG[NN * HD];
__device__ __half g_M[NN * HD];
__device__ float g_y[NG * HD];
__device__ int g_cnt[NN];
__device__ int g_cur[NN];
__device__ int g_off[NN + 1];
__device__ int g_elist[NE];
__device__ int g_bsum[128];
__device__ int g_bpre[128];
// single fp16 weights: [We1|Wg] concat per conv, WpT, We2T per conv
#define WCAT(c) ((c) * 49152)
#define WPT 147456
#define WE2(c) (163840 + (c) * 32768)
__device__ __half g_Wf[262144];

__device__ __forceinline__ float sp_(float x) {
    return fmaxf(x, 0.f) + __logf(1.f + __expf(-fabsf(x)));
}
__device__ __forceinline__ float sigm_(float x) {
    return 1.f / (1.f + __expf(-x));
}

__global__ void k_wsplit_all(const float* __restrict__ Wg, const float* __restrict__ We1,
                             const float* __restrict__ We2, const float* __restrict__ Wp) {
    int i = blockIdx.x * blockDim.x + threadIdx.x;
    if (i >= 262144) return;
    float w;
    if (i < 147456) {
        int c = i / 49152, j = i % 49152;
        int n = j / HD, k = j % HD;
        w = (n < EF) ? We1[c * 32768 + k * EF + n]
                     : Wg[c * 16384 + k * HD + (n - EF)];
    } else if (i < 163840) {
        int j = i - 147456;
        int n = j / HD, k = j % HD;
        w = Wp[k * HD + n];
    } else {
        int j = i - 163840;
        int c = j / 32768, jj = j % 32768;
        int n = jj >> 8, k = jj & 255;
        w = We2[c * 32768 + k * HD + n];
    }
    g_Wf[i] = __float2half_rn(w);
}

__global__ void k_zero_misc() {
    int i = blockIdx.x * blockDim.x + threadIdx.x;
    if (i < NN) {
        g_cnt[i] = 0;
        g_cur[i] = 0;
    }
    if (i < NG * HD) g_y[i] = 0.f;
}

__global__ void k_hist(const int* __restrict__ tgt) {
    int i = blockIdx.x * blockDim.x + threadIdx.x;
    if (i < NE) atomicAdd(&g_cnt[tgt[i]], 1);
}

__global__ void k_scan1() {
    __shared__ int wsum[32];
    const int tid = threadIdx.x;
    const int lane = tid & 31;
    const int wid = tid >> 5;
    const int i = blockIdx.x * 1024 + tid;
    int v = (i < NN) ? g_cnt[i] : 0;
    int inc = v;
#pragma unroll
    for (int d = 1; d < 32; d <<= 1) {
        int t = __shfl_up_sync(0xFFFFFFFFu, inc, d);
        if (lane >= d) inc += t;
    }
    if (lane == 31) wsum[wid] = inc;
    __syncthreads();
    if (wid == 0) {
        int w = wsum[lane];
        int wi = w;
#pragma unroll
        for (int d = 1; d < 32; d <<= 1) {
            int t = __shfl_up_sync(0xFFFFFFFFu, wi, d);
            if (lane >= d) wi += t;
        }
        wsum[lane] = wi - w;
    }
    __syncthreads();
    int binc = wsum[wid] + inc;
    if (i < NN) g_off[i + 1] = binc;
    if (tid == 1023) g_bsum[blockIdx.x] = binc;
}

__global__ void k_scan2() {
    __shared__ int ws[4];
    const int tid = threadIdx.x;
    const int lane = tid & 31;
    const int wid = tid >> 5;
    int v = (tid < NB_SCAN) ? g_bsum[tid] : 0;
    int inc = v;
#pragma unroll
    for (int d = 1; d < 32; d <<= 1) {
        int t = __shfl_up_sync(0xFFFFFFFFu, inc, d);
        if (lane >= d) inc += t;
    }
    if (lane == 31) ws[wid] = inc;
    __syncthreads();
    if (tid == 0) {
        int a = 0;
#pragma unroll
        for (int w = 0; w < 4; w++) {
            int t = ws[w];
            ws[w] = a;
            a += t;
        }
    }
    __syncthreads();
    if (tid < NB_SCAN) g_bpre[tid] = ws[wid] + inc - v;
}

__global__ void k_scan3() {
    int i = blockIdx.x * blockDim.x + threadIdx.x;
    if (i == 0) g_off[0] = 0;
    if (i < NN) g_off[i + 1] += g_bpre[i >> 10];
}

__global__ void k_fill(const int* __restrict__ src, const int* __restrict__ tgt) {
    int i = blockIdx.x * blockDim.x + threadIdx.x;
    if (i >= NE) return;
    int t = tgt[i];
    int p = g_off[t] + atomicAdd(&g_cur[t], 1);
    g_elist[p] = src[i];
}

__global__ void k_embed(const int* __restrict__ nodes, const float* __restrict__ embed) {
    int i = blockIdx.x * blockDim.x + threadIdx.x;
    if (i >= NN * (HD / 4)) return;
    int node = nodes[i >> 5];
    float4 v = ((const float4*)embed)[node * 32 + (i & 31)];
    ((float4*)g_x)[i] = v;
    ((__half2*)g_xf)[i * 2] = __floats2half2_rn(v.x, v.y);
    ((__half2*)g_xf)[i * 2 + 1] = __floats2half2_rn(v.z, v.w);
}

// ---- PTX helpers ----
#define LDA 40

__device__ __forceinline__ void cp16(uint32_t dst, const void* src, bool pred) {
    int sz = pred ? 16 : 0;
    asm volatile("cp.async.cg.shared.global [%0], [%1], 16, %2;"
                 :: "r"(dst), "l"(src), "r"(sz));
}
__device__ __forceinline__ void cp_commit() {
    asm volatile("cp.async.commit_group;");
}
template <int N_>
__device__ __forceinline__ void cp_wait() {
    asm volatile("cp.async.wait_group %0;" :: "n"(N_));
}
__device__ __forceinline__ void ldm_x4(uint32_t addr, uint32_t r[4]) {
    asm volatile("ldmatrix.sync.aligned.m8n8.x4.shared.b16 {%0,%1,%2,%3},[%4];"
                 : "=r"(r[0]), "=r"(r[1]), "=r"(r[2]), "=r"(r[3]) : "r"(addr));
}
__device__ __forceinline__ void mma_f16(float c[4], const uint32_t a[4],
                                        uint32_t b0, uint32_t b1) {
    asm volatile(
        "mma.sync.aligned.m16n8k16.row.col.f32.f16.f16.f32 "
        "{%0,%1,%2,%3},{%4,%5,%6,%7},{%8,%9},{%0,%1,%2,%3};"
        : "+f"(c[0]), "+f"(c[1]), "+f"(c[2]), "+f"(c[3])
        : "r"(a[0]), "r"(a[1]), "r"(a[2]), "r"(a[3]), "r"(b0), "r"(b1));
}

// ======================================================================
// A-RESIDENT fp16 single-term GEMM: 128xK A panel in smem once, loop over
// NTILES 64-wide n-tiles, B single fp16 double-buffered.
// EPI: 3 atomicAdd Cf[gidx] ; 4 merged (n<256: Af softplus | sG sigmoid)
// ======================================================================
template <int EPI, int NTILES, int KT_>
__global__ void __launch_bounds__(256) k_g16ar(
    const __half* __restrict__ A, const __half* __restrict__ B,
    float* __restrict__ Cf, const int* __restrict__ gidx,
    __half* __restrict__ Out16, __half* __restrict__ Out2, int M) {
    constexpr int K = KT_;
    constexpr int T = K / 32;
    constexpr int LDA2 = K + 8;

    __shared__ __half sAr[128 * LDA2];
    __shared__ __half sB[2][64 * LDA];

    const int tid = threadIdx.x;
    const int lane = tid & 31;
    const int warp = tid >> 5;
    const int wm = warp >> 1;
    const int wn = warp & 1;
    const int m0 = blockIdx.x * 128;

    uint32_t aBr = (uint32_t)__cvta_generic_to_shared(sAr);
    uint32_t bB[2];
#pragma unroll
    for (int st = 0; st < 2; st++)
        bB[st] = (uint32_t)__cvta_generic_to_shared(&sB[st][0]);

    const int b_r = tid >> 2;
    const int b_kc = (tid & 3) * 8;
    const uint32_t bOff = (uint32_t)(b_r * LDA + b_kc) * 2u;

    const int a_row = ((lane >> 3) & 1) * 8 + (lane & 7);
    const int a_kof = (lane >> 4) * 8;
    const int b_row = ((lane >> 4) & 1) * 8 + (lane & 7);
    const int b_kof = ((lane >> 3) & 1) * 8;

    // load entire A panel
    constexpr int CPR = K / 8;
#pragma unroll
    for (int it = 0; it < (128 * CPR) / 256; it++) {
        int idx = tid + it * 256;
        int row = idx / CPR;
        int cc = idx % CPR;
        bool p = (m0 + row) < M;
        const __half* src = A + (p ? ((long)(m0 + row) * K + cc * 8) : 0);
        cp16(aBr + (uint32_t)(row * LDA2 + cc * 8) * 2u, src, p);
    }
    cp_commit();

#define LOAD_B(st, k0, nn0)                                           \
    do {                                                              \
        const __half* pb = B + (long)((nn0) + b_r) * K + b_kc + (k0); \
        cp16(bB[st] + bOff, pb, true);                                \
    } while (0)

    LOAD_B(0, 0, 0);
    cp_commit();

#pragma unroll
    for (int nt = 0; nt < NTILES; nt++) {
        const int n0 = nt * 64;
        float acc[2][4][4];
#pragma unroll
        for (int i = 0; i < 2; i++)
#pragma unroll
            for (int j = 0; j < 4; j++)
#pragma unroll
                for (int q = 0; q < 4; q++) acc[i][j][q] = 0.f;

#pragma unroll
        for (int kt = 0; kt < T; kt++) {
            bool more = (kt + 1 < T) || (nt + 1 < NTILES);
            if (kt + 1 < T)
                LOAD_B((kt + 1) & 1, (kt + 1) * 32, n0);
            else if (nt + 1 < NTILES)
                LOAD_B(0, 0, n0 + 64);  // T even
            cp_commit();
            if (more) cp_wait<1>();
            else cp_wait<0>();
            __syncthreads();

            const int st = kt & 1;
#pragma unroll
            for (int ks = 0; ks < 32; ks += 16) {
                uint32_t fa[2][4], fb[2][4];
#pragma unroll
                for (int mt = 0; mt < 2; mt++) {
                    uint32_t off = (uint32_t)((wm * 32 + mt * 16 + a_row) * LDA2 +
                                              kt * 32 + ks + a_kof) * 2u;
                    ldm_x4(aBr + off, fa[mt]);
                }
#pragma unroll
                for (int np = 0; np < 2; np++) {
                    uint32_t off = (uint32_t)((wn * 32 + np * 16 + b_row) * LDA +
                                              ks + b_kof) * 2u;
                    ldm_x4(bB[st] + off, fb[np]);
                }
#pragma unroll
                for (int mt = 0; mt < 2; mt++) {
#pragma unroll
                    for (int nt2 = 0; nt2 < 4; nt2++) {
                        uint32_t b0 = fb[nt2 >> 1][(nt2 & 1) * 2];
                        uint32_t b1 = fb[nt2 >> 1][(nt2 & 1) * 2 + 1];
                        mma_f16(acc[mt][nt2], fa[mt], b0, b1);
                    }
                }
            }
            __syncthreads();
        }

#pragma unroll
        for (int mt = 0; mt < 2; mt++) {
#pragma unroll
            for (int nt2 = 0; nt2 < 4; nt2++) {
                int rbase = m0 + wm * 32 + mt * 16 + (lane >> 2);
                int col = n0 + wn * 32 + nt2 * 8 + (lane & 3) * 2;
                float* c = acc[mt][nt2];
#pragma unroll
                for (int half = 0; half < 2; half++) {
                    int row = rbase + half * 8;
                    if (row >= M) continue;
                    float v0 = c[half * 2], v1 = c[half * 2 + 1];
                    if (EPI == 4 && n0 < 256) {
                        long base = (long)row * 256 + col;
                        *reinterpret_cast<__half2*>(&Out16[base]) =
                            __floats2half2_rn(sp_(v0), sp_(v1));
                    } else if (EPI == 4) {
                        long base = (long)row * HD + (col - 256);
                        *reinterpret_cast<__half2*>(&Out2[base]) =
                            __floats2half2_rn(sigm_(v0), sigm_(v1));
                    } else {  // EPI == 3
                        int seg = gidx[row];
                        atomicAdd(reinterpret_cast<float2*>(&Cf[(long)seg * HD + col]),
                                  make_float2(v0, v1));
                    }
                }
            }
        }
    }
#undef LOAD_B
}

// ======================================================================
// Message GEMM (single-term fp16): M = Gb16 * softplus(A @ B^T), K=256
// ======================================================================
template <int KT_>
__global__ void __launch_bounds__(256) k_g16(
    const __half* __restrict__ A, const __half* __restrict__ B,
    const __half* __restrict__ Gb16, __half* __restrict__ Out16, int M) {
    constexpr int K = KT_;
    constexpr int T = K / 32;

    __shared__ __half sA[2][128 * LDA];
    __shared__ __half sB[2][64 * LDA];

    const int tid = threadIdx.x;
    const int lane = tid & 31;
    const int warp = tid >> 5;
    const int wm = warp >> 1;
    const int wn = warp & 1;
    const int m0 = blockIdx.y * 128;
    const int n0 = blockIdx.x * 64;

    float acc[2][4][4];
#pragma unroll
    for (int i = 0; i < 2; i++)
#pragma unroll
        for (int j = 0; j < 4; j++)
#pragma unroll
            for (int q = 0; q < 4; q++) acc[i][j][q] = 0.f;

    uint32_t aB[2], bB[2];
#pragma unroll
    for (int st = 0; st < 2; st++) {
        aB[st] = (uint32_t)__cvta_generic_to_shared(&sA[st][0]);
        bB[st] = (uint32_t)__cvta_generic_to_shared(&sB[st][0]);
    }

    const int a_r0 = tid >> 2;
    const int a_kc = (tid & 3) * 8;
    const int b_r = tid >> 2;
    const int b_kc = (tid & 3) * 8;

    const int a_row = ((lane >> 3) & 1) * 8 + (lane & 7);
    const int a_kof = (lane >> 4) * 8;
    const int b_row = ((lane >> 4) & 1) * 8 + (lane & 7);
    const int b_kof = ((lane >> 3) & 1) * 8;

    const bool pA0 = (m0 + a_r0) < M;
    const bool pA1 = (m0 + a_r0 + 64) < M;
    const uint32_t aOff0 = (uint32_t)(a_r0 * LDA + a_kc) * 2u;
    const uint32_t aOff1 = (uint32_t)((a_r0 + 64) * LDA + a_kc) * 2u;
    const uint32_t bOff = (uint32_t)(b_r * LDA + b_kc) * 2u;
    const __half* gA0 = A + (pA0 ? (long)(m0 + a_r0) * K + a_kc : 0);
    const __half* gA1 = A + (pA1 ? (long)(m0 + a_r0 + 64) * K + a_kc : 0);
    const __half* gB = B + (long)(n0 + b_r) * K + b_kc;

#define LOAD_STAGE(st, k0)                        \
    do {                                          \
        cp16(aB[st] + aOff0, gA0 + (k0), pA0);    \
        cp16(aB[st] + aOff1, gA1 + (k0), pA1);    \
        cp16(bB[st] + bOff, gB + (k0), true);     \
        cp_commit();                              \
    } while (0)

    LOAD_STAGE(0, 0);

#pragma unroll
    for (int kt = 0; kt < T; kt++) {
        if (kt + 1 < T) {
            LOAD_STAGE((kt + 1) & 1, (kt + 1) * 32);
            cp_wait<1>();
        } else {
            cp_wait<0>();
        }
        __syncthreads();

        const int st = kt & 1;
#pragma unroll
        for (int ks = 0; ks < 32; ks += 16) {
            uint32_t fa[2][4], fb[2][4];
#pragma unroll
            for (int mt = 0; mt < 2; mt++) {
                uint32_t off = (uint32_t)((wm * 32 + mt * 16 + a_row) * LDA + ks + a_kof) * 2u;
                ldm_x4(aB[st] + off, fa[mt]);
            }
#pragma unroll
            for (int np = 0; np < 2; np++) {
                uint32_t off = (uint32_t)((wn * 32 + np * 16 + b_row) * LDA + ks + b_kof) * 2u;
                ldm_x4(bB[st] + off, fb[np]);
            }
#pragma unroll
            for (int mt = 0; mt < 2; mt++) {
#pragma unroll
                for (int nt = 0; nt < 4; nt++) {
                    uint32_t b0 = fb[nt >> 1][(nt & 1) * 2];
                    uint32_t b1 = fb[nt >> 1][(nt & 1) * 2 + 1];
                    mma_f16(acc[mt][nt], fa[mt], b0, b1);
                }
            }
        }
        __syncthreads();
    }
#undef LOAD_STAGE

#pragma unroll
    for (int mt = 0; mt < 2; mt++) {
#pragma unroll
        for (int nt = 0; nt < 4; nt++) {
            int rbase = m0 + wm * 32 + mt * 16 + (lane >> 2);
            int col = n0 + wn * 32 + nt * 8 + (lane & 3) * 2;
            float* c = acc[mt][nt];
#pragma unroll
            for (int half = 0; half < 2; half++) {
                int row = rbase + half * 8;
                if (row >= M) continue;
                long base = (long)row * HD + col;
                float2 g2 = __half22float2(
                    *reinterpret_cast<const __half2*>(&Gb16[base]));
                *reinterpret_cast<__half2*>(&Out16[base]) =
                    __floats2half2_rn(g2.x * sp_(c[half * 2]), g2.y * sp_(c[half * 2 + 1]));
            }
        }
    }
}

// ---- CSR gather + fused node update ----
__global__ void __launch_bounds__(256) k_gather() {
    int warp = (blockIdx.x * 256 + threadIdx.x) >> 5;
    int lane = threadIdx.x & 31;
    if (warp >= NN) return;
    int beg = g_off[warp], end = g_off[warp + 1];

    float4 acc = make_float4(0.f, 0.f, 0.f, 0.f);
    int e = beg;
    for (; e + 1 < end; e += 2) {
        int s0 = g_elist[e], s1 = g_elist[e + 1];
        float2 p0 = *reinterpret_cast<const float2*>(&g_M[(long)s0 * HD + lane * 4]);
        float2 p1 = *reinterpret_cast<const float2*>(&g_M[(long)s1 * HD + lane * 4]);
        const __half2* h0 = reinterpret_cast<const __half2*>(&p0);
        const __half2* h1 = reinterpret_cast<const __half2*>(&p1);
        float2 a0 = __half22float2(h0[0]), b0 = __half22float2(h0[1]);
        float2 a1 = __half22float2(h1[0]), b1 = __half22float2(h1[1]);
        acc.x += a0.x + a1.x;
        acc.y += a0.y + a1.y;
        acc.z += b0.x + b1.x;
        acc.w += b0.y + b1.y;
    }
    if (e < end) {
        int s0 = g_elist[e];
        float2 p0 = *reinterpret_cast<const float2*>(&g_M[(long)s0 * HD + lane * 4]);
        const __half2* h0 = reinterpret_cast<const __half2*>(&p0);
        float2 a0 = __half22float2(h0[0]), b0 = __half22float2(h0[1]);
        acc.x += a0.x;
        acc.y += a0.y;
        acc.z += b0.x;
        acc.w += b0.y;
    }

    int i4 = warp * 32 + lane;
    float4 x = ((float4*)g_x)[i4];
    x.x += sp_(acc.x);
    x.y += sp_(acc.y);
    x.z += sp_(acc.z);
    x.w += sp_(acc.w);
    ((float4*)g_x)[i4] = x;
    ((__half2*)g_xf)[i4 * 2] = __floats2half2_rn(x.x, x.y);
    ((__half2*)g_xf)[i4 * 2 + 1] = __floats2half2_rn(x.z, x.w);
}

__global__ void k_mlp(const float* __restrict__ counts,
                      const float* __restrict__ Wfc1, const float* __restrict__ bfc1,
                      const float* __restrict__ Wfc2, const float* __restrict__ bfc2,
                      const float* __restrict__ Wr, const float* __restrict__ br,
                      float* __restrict__ out) {
    __shared__ float s0[HD];
    __shared__ float s1[HD];
    __shared__ float red[HD];
    int g = blockIdx.x, t = threadIdx.x;

    float yv = g_y[g * HD + t] / counts[g];
    s0[t] = sp_(yv);
    __syncthreads();

    float acc = bfc1[t];
#pragma unroll 8
    for (int k = 0; k < HD; k++) acc += s0[k] * Wfc1[k * HD + t];
    s1[t] = sp_(acc);
    __syncthreads();

    acc = bfc2[t];
#pragma unroll 8
    for (int k = 0; k < HD; k++) acc += s1[k] * Wfc2[k * HD + t];
    float h2 = sp_(acc);

    red[t] = h2 * Wr[t];
    __syncthreads();
    for (int s = HD / 2; s > 0; s >>= 1) {
        if (t < s) red[t] += red[t + s];
        __syncthreads();
    }
    if (t == 0) out[g] = red[0] + br[0];
}

extern "C" void kernel_launch(void* const* d_in, const int* in_sizes, int n_in,
                              void* d_out, int out_size) {
    const int* nodes = (const int*)d_in[0];
    const int* esrc = (const int*)d_in[1];
    const int* etgt = (const int*)d_in[2];
    const int* gidx = (const int*)d_in[3];
    const float* counts = (const float*)d_in[4];
    const float* embed = (const float*)d_in[5];
    const float* Wg = (const float*)d_in[6];
    const float* We1 = (const float*)d_in[7];
    const float* We2 = (const float*)d_in[8];
    const float* Wp = (const float*)d_in[9];
    const float* Wfc1 = (const float*)d_in[10];
    const float* bfc1 = (const float*)d_in[11];
    const float* Wfc2 = (const float*)d_in[12];
    const float* bfc2 = (const float*)d_in[13];
    const float* Wr = (const float*)d_in[14];
    const float* br = (const float*)d_in[15];
    float* out = (float*)d_out;

    __half *pxf, *pAf, *pWf, *psG, *pM;
    float* py;
    cudaGetSymbolAddress((void**)&pxf, g_xf);
    cudaGetSymbolAddress((void**)&pAf, g_Af);
    cudaGetSymbolAddress((void**)&pWf, g_Wf);
    cudaGetSymbolAddress((void**)&psG, g_sG);
    cudaGetSymbolAddress((void**)&pM, g_M);
    cudaGetSymbolAddress((void**)&py, g_y);

    const int blocksM = (NN + 127) / 128;

    k_wsplit_all<<<(262144 + 255) / 256, 256>>>(Wg, We1, We2, Wp);
    k_zero_misc<<<(NN + 255) / 256, 256>>>();
    k_hist<<<(NE + 255) / 256, 256>>>(etgt);
    k_scan1<<<NB_SCAN, 1024>>>();
    k_scan2<<<1, 128>>>();
    k_scan3<<<(NN + 1023) / 1024, 1024>>>();
    k_fill<<<(NE + 255) / 256, 256>>>(esrc, etgt);
    {
        int n = NN * (HD / 4);
        k_embed<<<(n + 255) / 256, 256>>>(nodes, embed);
    }
    for (int i = 0; i < NCONV; i++) {
        // merged A-resident: sp(x@We1) -> Af AND sigmoid(x@Wg) -> sG
        k_g16ar<4, 6, HD><<<blocksM, 256>>>(
            pxf, pWf + WCAT(i), nullptr, nullptr, pAf, psG, NN);
        // M = sG * sp(A @ We2)
        k_g16<EF><<<dim3(HD / 64, blocksM), 256>>>(
            pAf, pWf + WE2(i), psG, pM, NN);
        k_gather<<<(NN + 7) / 8, 256>>>();
    }
    // pooling A-resident with fused segment atomics
    k_g16ar<3, 2, HD><<<blocksM, 256>>>(
        pxf, pWf + WPT, py, gidx, nullptr, nullptr, NN);
    k_mlp<<<NG, HD>>>(counts, Wfc1, bfc1, Wfc2, bfc2, Wr, br, out);
}